// round 7
// baseline (speedup 1.0000x reference)
#include <cuda_runtime.h>
#include <math.h>

#define CCH 512
#define BB  32
#define HW  4096
#define BN_EPS 1e-5f

// Per-(b,c) pooled values (already includes pos-embed term and /4096).
__device__ float g_pooled[BB * CCH];

// 49 bilinear pooling weights A[i]*A[j], computed host-side, passed by value.
struct PEW { float w[49]; };

// ---------------------------------------------------------------------------
// Kernel 1: pooled[b,c] = ( sum_{hw} x[b,c,:,:] + sum_k pe[c,k]*W[k] ) / 4096
// One block per (b,c). 256 threads * 4 float4, coalesced, MLP=4. ~86% of HBM.
// Triggers programmatic launch of the gemm kernel immediately so the gemm's
// cold conv_w DRAM fetch overlaps this kernel's tail waves.
// ---------------------------------------------------------------------------
__global__ __launch_bounds__(256) void reduce_x_kernel(
    const float* __restrict__ x, const float* __restrict__ pe, PEW pw)
{
    cudaTriggerProgrammaticLaunchCompletion();

    const int bc = blockIdx.x;
    const float4* p = reinterpret_cast<const float4*>(x) + (size_t)bc * (HW / 4);
    const int t = threadIdx.x;

    float4 a = p[t];
    float4 b = p[t + 256];
    float4 c = p[t + 512];
    float4 d = p[t + 768];

    float s = (a.x + a.y) + (a.z + a.w)
            + (b.x + b.y) + (b.z + b.w)
            + (c.x + c.y) + (c.z + c.w)
            + (d.x + d.y) + (d.z + d.w);

    #pragma unroll
    for (int off = 16; off > 0; off >>= 1)
        s += __shfl_xor_sync(0xffffffffu, s, off);

    __shared__ float ws[8];
    const int w = t >> 5, l = t & 31;
    if (l == 0) ws[w] = s;
    __syncthreads();

    if (t < 32) {
        const int cch = bc & (CCH - 1);
        const float* pc = pe + cch * 49;
        float v = (l < 8) ? ws[l] : 0.f;
        v = fmaf(pc[l], pw.w[l], v);                       // terms 0..31
        if (l < 17) v = fmaf(pc[l + 32], pw.w[l + 32], v); // terms 32..48
        #pragma unroll
        for (int off = 16; off > 0; off >>= 1)
            v += __shfl_xor_sync(0xffffffffu, v, off);
        if (l == 0) g_pooled[bc] = v * (1.0f / (float)HW);
    }
}

// ---------------------------------------------------------------------------
// Kernel 2 (PDL): prefetch conv_w row segments into registers and BN params
// BEFORE cudaGridDependencySynchronize() — this DRAM traffic overlaps K1.
// After the sync, only smem staging + 128 FMA/lane + shuffle reduce remain.
// Block = 8 outputs (one per warp) x 8 batches; grid = 64 o-tiles x 4 b-groups.
// ---------------------------------------------------------------------------
__global__ __launch_bounds__(256) void gemm_kernel(
    const float* __restrict__ conv_w,
    const float* __restrict__ conv_b,
    const float* __restrict__ gamma,
    const float* __restrict__ beta,
    const float* __restrict__ rmean,
    const float* __restrict__ rvar,
    float* __restrict__ out)
{
    const int b0 = (blockIdx.x & 3) * 8;        // batch group: 8 batches
    const int o0 = (blockIdx.x >> 2) * 8;       // output tile: 8 outputs
    const int t  = threadIdx.x;
    const int w  = t >> 5, l = t & 31;
    const int o  = o0 + w;

    // ---- Prefetch phase (independent of K1's output) ----
    const float* wr = conv_w + (size_t)o * CCH;
    float wreg[16];
    #pragma unroll
    for (int i = 0; i < 16; i++)
        wreg[i] = wr[l + 32 * i];

    float bias = 0.f, g = 0.f, bt = 0.f, mu = 0.f, var1 = 1.f;
    if (l == 0) {
        bias = conv_b[o]; g = gamma[o]; bt = beta[o];
        mu = rmean[o];    var1 = rvar[o];
    }

    // ---- Wait for K1 completion (g_pooled visible) ----
    cudaGridDependencySynchronize();

    __shared__ float sp[8 * CCH];
    {
        const float4* src = reinterpret_cast<const float4*>(g_pooled + b0 * CCH);
        float4* dst = reinterpret_cast<float4*>(sp);
        #pragma unroll
        for (int i = 0; i < 4; i++)
            dst[t + 256 * i] = src[t + 256 * i];
    }
    __syncthreads();

    float acc[8];
    #pragma unroll
    for (int b = 0; b < 8; b++) {
        const float* spb = sp + b * CCH;
        float a = 0.f;
        #pragma unroll
        for (int i = 0; i < 16; i++)
            a = fmaf(spb[l + 32 * i], wreg[i], a);
        acc[b] = a;
    }

    #pragma unroll
    for (int off = 16; off > 0; off >>= 1) {
        #pragma unroll
        for (int b = 0; b < 8; b++)
            acc[b] += __shfl_xor_sync(0xffffffffu, acc[b], off);
    }

    if (l == 0) {
        const float inv = rsqrtf(var1 + BN_EPS);
        #pragma unroll
        for (int b = 0; b < 8; b++) {
            float y = g * (acc[b] + bias - mu) * inv + bt;
            out[(b0 + b) * CCH + o] = fmaxf(y, 0.f);
        }
    }
}

extern "C" void kernel_launch(void* const* d_in, const int* in_sizes, int n_in,
                              void* d_out, int out_size) {
    const float* x      = (const float*)d_in[0];
    const float* pe     = (const float*)d_in[1];
    const float* conv_w = (const float*)d_in[2];
    const float* conv_b = (const float*)d_in[3];
    const float* gamma  = (const float*)d_in[4];
    const float* beta   = (const float*)d_in[5];
    const float* rmean  = (const float*)d_in[6];
    const float* rvar   = (const float*)d_in[7];
    float* out = (float*)d_out;

    // Host-side: bilinear 7->64 (half-pixel centers) column sums A[7],
    // then outer-product weights W[i*7+j] = A[i]*A[j].
    float A[7] = {0, 0, 0, 0, 0, 0, 0};
    for (int o = 0; o < 64; o++) {
        float s = (o + 0.5f) * (7.0f / 64.0f) - 0.5f;
        if (s <= 0.f)       A[0] += 1.f;
        else if (s >= 6.f)  A[6] += 1.f;
        else {
            int i0 = (int)floorf(s);
            float f = s - (float)i0;
            A[i0]     += 1.f - f;
            A[i0 + 1] += f;
        }
    }
    PEW pw;
    for (int i = 0; i < 7; i++)
        for (int j = 0; j < 7; j++)
            pw.w[i * 7 + j] = A[i] * A[j];

    reduce_x_kernel<<<BB * CCH, 256>>>(x, pe, pw);

    // Launch gemm with Programmatic Dependent Launch so its prefetch phase
    // overlaps reduce_x_kernel's tail.
    cudaLaunchConfig_t cfg = {};
    cfg.gridDim  = dim3(64 * 4);
    cfg.blockDim = dim3(256);
    cfg.dynamicSmemBytes = 0;
    cfg.stream = 0;
    cudaLaunchAttribute attr[1];
    attr[0].id = cudaLaunchAttributeProgrammaticStreamSerialization;
    attr[0].val.programmaticStreamSerializationAllowed = 1;
    cfg.attrs = attr;
    cfg.numAttrs = 1;
    cudaLaunchKernelEx(&cfg, gemm_kernel,
                       conv_w, conv_b, gamma, beta, rmean, rvar, out);
}